// round 1
// baseline (speedup 1.0000x reference)
#include <cuda_runtime.h>
#include <math.h>

// Problem constants (fixed by setup_inputs)
#define BB     8
#define SS     2048
#define CC     8
#define DD     9
#define WIN    60
#define NTOT   (BB * SS)      // 16384 windows
#define SIGCH  285            // 9 + 36 + 240
#define H2C    512
#define H1C    256
#define RB     16             // rows per MLP block
#define NW     8              // warps per sig block

// Scratch (static __device__ allocation is allowed)
__device__ float g_feats[NTOT * SIGCH];
__device__ int   g_l2[36];
__device__ int   g_l3[240];

// ---------------------------------------------------------------------------
// Setup: enumerate Lyndon indices in the exact reference ordering.
// Tuple lexicographic compare == base-9 integer compare of the encoding.
// ---------------------------------------------------------------------------
__global__ void lyndon_setup_kernel() {
    if (threadIdx.x == 0 && blockIdx.x == 0) {
        int n2 = 0, n3 = 0;
        for (int i = 0; i < DD; i++)
            for (int j = 0; j < DD; j++)
                if (i < j) g_l2[n2++] = i * 9 + j;
        for (int i = 0; i < DD; i++)
            for (int j = 0; j < DD; j++)
                for (int k = 0; k < DD; k++) {
                    int e  = (i * 9 + j) * 9 + k;
                    int r1 = (j * 9 + k) * 9 + i;
                    int r2 = (k * 9 + i) * 9 + j;
                    if (e < r1 && e < r2) g_l3[n3++] = e;
                }
    }
}

// ---------------------------------------------------------------------------
// Kernel A: log-signature features. One warp per window.
// Lanes 0..26: lane owns i = lane/3, j in {3*(lane%3) .. +2}.
// Per-lane state: s1i (S1[i]), S2r[3], S3r[3][9]  -> no cross-lane comm in scan.
// ---------------------------------------------------------------------------
__global__ __launch_bounds__(256) void sig_kernel(const float* __restrict__ x) {
    // vs3 row: first used as increment buffer (60 steps x 12 floats = 720),
    // then reused to hold S3 (729 floats). Row stride 732 floats (2928B, 16B-aligned).
    __shared__ float vs3[NW][732];
    __shared__ float s2s[NW][81];
    __shared__ float s1s[NW][12];

    const int w    = threadIdx.x >> 5;
    const int lane = threadIdx.x & 31;
    const int n    = blockIdx.x * NW + w;
    const int bb   = n >> 11;      // / 2048
    const int ss   = n & 2047;

    float* vbuf = vs3[w];
    const float inv59 = 1.0f / 59.0f;

    // ---- Stage window increments into shared ----
    for (int step = lane; step < WIN; step += 32) {
        int pos  = ss + step - (WIN - 1);
        int posc = pos < 0 ? 0 : pos;
        const float* xr = x + ((size_t)bb * SS + posc) * CC;
        float4 a0 = *(const float4*)(xr);
        float4 a1 = *(const float4*)(xr + 4);
        float vt;
        float4 d0, d1;
        if (step == 0) {
            vt = 0.0f;                 // t[0] = 0, prepend-zero diff -> aug[0]
            d0 = a0; d1 = a1;
        } else {
            vt = inv59;
            int pm  = pos - 1;
            int pmc = pm < 0 ? 0 : pm;
            const float* xp = x + ((size_t)bb * SS + pmc) * CC;
            float4 b0 = *(const float4*)(xp);
            float4 b1 = *(const float4*)(xp + 4);
            d0.x = a0.x - b0.x; d0.y = a0.y - b0.y; d0.z = a0.z - b0.z; d0.w = a0.w - b0.w;
            d1.x = a1.x - b1.x; d1.y = a1.y - b1.y; d1.z = a1.z - b1.z; d1.w = a1.w - b1.w;
        }
        float* vv = vbuf + step * 12;
        vv[0] = vt;
        vv[1] = d0.x; vv[2] = d0.y; vv[3] = d0.z; vv[4] = d0.w;
        vv[5] = d1.x; vv[6] = d1.y; vv[7] = d1.z; vv[8] = d1.w;
    }
    __syncwarp();

    // ---- Chen scan ----
    float S3r[3][9];
    float S2r[3];
    float s1i = 0.0f;
    const int li = lane / 3;
    const int jb = (lane % 3) * 3;

    if (lane < 27) {
#pragma unroll
        for (int c = 0; c < 3; c++) {
            S2r[c] = 0.0f;
#pragma unroll
            for (int k = 0; k < 9; k++) S3r[c][k] = 0.0f;
        }
#pragma unroll 2
        for (int step = 0; step < WIN; step++) {
            const float* vv = vbuf + step * 12;
            float4 va = *(const float4*)(vv);
            float4 vb = *(const float4*)(vv + 4);
            float  v8 = vv[8];
            float  vi = vv[li];                       // LDS broadcast within i-group
            float bcoef = fmaf(vi, 1.0f / 6.0f, 0.5f * s1i);
            float ccoef = fmaf(vi, 0.5f, s1i);
#pragma unroll
            for (int c = 0; c < 3; c++) {
                float vj = vv[jb + c];
                float a = fmaf(bcoef, vj, S2r[c]);    // S2 + (0.5*S1i + vi/6)*vj
                S3r[c][0] = fmaf(a, va.x, S3r[c][0]);
                S3r[c][1] = fmaf(a, va.y, S3r[c][1]);
                S3r[c][2] = fmaf(a, va.z, S3r[c][2]);
                S3r[c][3] = fmaf(a, va.w, S3r[c][3]);
                S3r[c][4] = fmaf(a, vb.x, S3r[c][4]);
                S3r[c][5] = fmaf(a, vb.y, S3r[c][5]);
                S3r[c][6] = fmaf(a, vb.z, S3r[c][6]);
                S3r[c][7] = fmaf(a, vb.w, S3r[c][7]);
                S3r[c][8] = fmaf(a, v8,   S3r[c][8]);
                S2r[c] = fmaf(ccoef, vj, S2r[c]);     // S2 + (S1i + 0.5*vi)*vj
            }
            s1i += vi;
        }
    }
    __syncwarp();

    // ---- Dump state to shared (vs3 row is now free to hold S3) ----
    if (lane < 27) {
#pragma unroll
        for (int c = 0; c < 3; c++) {
            int p = li * 9 + jb + c;
            s2s[w][p] = S2r[c];
#pragma unroll
            for (int k = 0; k < 9; k++) vs3[w][p * 9 + k] = S3r[c][k];
        }
        if ((lane % 3) == 0) s1s[w][li] = s1i;
    }
    __syncwarp();

    // ---- Log-signature + Lyndon gather ----
    const float* S3s = vs3[w];
    const float* S2p = s2s[w];
    const float* S1p = s1s[w];
    float* fo = g_feats + (size_t)n * SIGCH;

    if (lane < 9) fo[lane] = S1p[lane];

    for (int t = lane; t < 36; t += 32) {
        int e = g_l2[t];
        int i = e / 9, j = e % 9;
        fo[9 + t] = S2p[e] - 0.5f * S1p[i] * S1p[j];
    }
    for (int t = lane; t < 240; t += 32) {
        int e  = g_l3[t];
        int k  = e % 9;
        int ij = e / 9;
        int j  = ij % 9;
        int i  = ij / 9;
        float v = S3s[e]
                - 0.5f * (S1p[i] * S2p[j * 9 + k] + S2p[ij] * S1p[k])
                + S1p[i] * S1p[j] * S1p[k] * (1.0f / 3.0f);
        fo[45 + t] = v;
    }
}

// ---------------------------------------------------------------------------
// Packed fp32x2 helpers (FFMA2 — Blackwell packed fp32, PTX-only)
// ---------------------------------------------------------------------------
__device__ __forceinline__ unsigned long long pack2(float lo, float hi) {
    unsigned long long r;
    asm("mov.b64 %0, {%1, %2};" : "=l"(r) : "f"(lo), "f"(hi));
    return r;
}
__device__ __forceinline__ void unpack2(unsigned long long v, float& lo, float& hi) {
    asm("mov.b64 {%0, %1}, %2;" : "=f"(lo), "=f"(hi) : "l"(v));
}
__device__ __forceinline__ void ffma2(unsigned long long& d, unsigned long long a,
                                      unsigned long long b) {
    asm("fma.rn.f32x2 %0, %1, %2, %0;" : "+l"(d) : "l"(a), "l"(b));
}

__device__ __forceinline__ float gelu_exact(float v) {
    return 0.5f * v * (1.0f + erff(v * 0.70710678118654752f));
}

// ---------------------------------------------------------------------------
// Kernel B: fused MLP. 16 rows per 256-thread block.
// Shared: fs (k-major, [285][16], stride 16) ; hs (k-major, [512][stride 20]).
// k-major layout -> row-pairs load directly as 64-bit FFMA2 operands.
// ---------------------------------------------------------------------------
#define FS_STRIDE 16
#define HS_STRIDE 20
#define SMEM_MLP  ((288 * FS_STRIDE + H2C * HS_STRIDE + 32) * 4)

__global__ __launch_bounds__(256) void mlp_kernel(
    const float* __restrict__ w1, const float* __restrict__ b1,
    const float* __restrict__ lng, const float* __restrict__ lnb,
    const float* __restrict__ w2, const float* __restrict__ b2,
    float* __restrict__ out)
{
    extern __shared__ float sm[];
    float* fs  = sm;                                 // [285][16] k-major
    float* hs  = sm + 288 * FS_STRIDE;               // [512][20] k-major
    float* mus = hs + H2C * HS_STRIDE;               // [16]
    float* rsd = mus + RB;                           // [16]

    const int j    = threadIdx.x;                    // 0..255
    const int row0 = blockIdx.x * RB;
    const float* frow = g_feats + (size_t)row0 * SIGCH;

    // Load 16 feature rows, transposed to k-major
    for (int idx = j; idx < RB * SIGCH; idx += 256) {
        int r = idx / SIGCH;
        int k = idx - r * SIGCH;
        fs[k * FS_STRIDE + r] = frow[idx];
    }
    __syncthreads();

    // ---- GEMM1: h[r][j], h[r][j+256] for 16 rows, packed row-pairs ----
    unsigned long long accA[8], accB[8];
#pragma unroll
    for (int p = 0; p < 8; p++) { accA[p] = 0ull; accB[p] = 0ull; }

    const float* w1a = w1 + j;
    const float* w1b = w1 + 256 + j;
#pragma unroll 2
    for (int k = 0; k < SIGCH; k++) {
        float wa = w1a[(size_t)k * H2C];
        float wb = w1b[(size_t)k * H2C];
        unsigned long long pa = pack2(wa, wa);
        unsigned long long pb = pack2(wb, wb);
        const ulonglong2* fp = (const ulonglong2*)(fs + k * FS_STRIDE);
#pragma unroll
        for (int q = 0; q < 4; q++) {
            ulonglong2 f = fp[q];                    // rows 4q..4q+3 at column k
            ffma2(accA[2 * q],     f.x, pa);
            ffma2(accA[2 * q + 1], f.y, pa);
            ffma2(accB[2 * q],     f.x, pb);
            ffma2(accB[2 * q + 1], f.y, pb);
        }
    }

    // ---- bias + exact GELU, store k-major into hs ----
    {
        float bA = b1[j], bBv = b1[j + 256];
#pragma unroll
        for (int p = 0; p < 8; p++) {
            float lo, hi;
            unpack2(accA[p], lo, hi);
            lo = gelu_exact(lo + bA);
            hi = gelu_exact(hi + bA);
            hs[j * HS_STRIDE + 2 * p]     = lo;
            hs[j * HS_STRIDE + 2 * p + 1] = hi;
            unpack2(accB[p], lo, hi);
            lo = gelu_exact(lo + bBv);
            hi = gelu_exact(hi + bBv);
            hs[(j + 256) * HS_STRIDE + 2 * p]     = lo;
            hs[(j + 256) * HS_STRIDE + 2 * p + 1] = hi;
        }
    }
    __syncthreads();

    // ---- LayerNorm stats: warp wid handles rows 2*wid, 2*wid+1 ----
    {
        int wid = j >> 5, lane = j & 31;
#pragma unroll
        for (int rr = 0; rr < 2; rr++) {
            int r = wid * 2 + rr;
            float s = 0.0f, s2 = 0.0f;
            for (int kk = lane; kk < H2C; kk += 32) {
                float h = hs[kk * HS_STRIDE + r];
                s += h;
                s2 = fmaf(h, h, s2);
            }
#pragma unroll
            for (int off = 16; off; off >>= 1) {
                s  += __shfl_down_sync(0xffffffffu, s,  off);
                s2 += __shfl_down_sync(0xffffffffu, s2, off);
            }
            if (lane == 0) {
                float mu  = s * (1.0f / 512.0f);
                float var = s2 * (1.0f / 512.0f) - mu * mu;
                mus[r] = mu;
                rsd[r] = rsqrtf(var + 1e-5f);
            }
        }
    }
    __syncthreads();

    // ---- Normalize in place ----
    {
        float gA = lng[j], gB = lng[j + 256];
        float oA = lnb[j], oB = lnb[j + 256];
#pragma unroll
        for (int r = 0; r < RB; r++) {
            float mu = mus[r], rs = rsd[r];
            float a = hs[j * HS_STRIDE + r];
            hs[j * HS_STRIDE + r] = (a - mu) * rs * gA + oA;
            float bv = hs[(j + 256) * HS_STRIDE + r];
            hs[(j + 256) * HS_STRIDE + r] = (bv - mu) * rs * gB + oB;
        }
    }
    __syncthreads();

    // ---- GEMM2: out[r][j] ----
    unsigned long long acc2[8];
#pragma unroll
    for (int p = 0; p < 8; p++) acc2[p] = 0ull;

    const float* w2j = w2 + j;
#pragma unroll 2
    for (int kk = 0; kk < H2C; kk++) {
        float wv = w2j[(size_t)kk * H1C];
        unsigned long long wp = pack2(wv, wv);
        const ulonglong2* hp = (const ulonglong2*)(hs + kk * HS_STRIDE);
#pragma unroll
        for (int q = 0; q < 4; q++) {
            ulonglong2 h = hp[q];
            ffma2(acc2[2 * q],     h.x, wp);
            ffma2(acc2[2 * q + 1], h.y, wp);
        }
    }

    {
        float bo = b2[j];
#pragma unroll
        for (int p = 0; p < 8; p++) {
            float lo, hi;
            unpack2(acc2[p], lo, hi);
            out[(size_t)(row0 + 2 * p) * H1C + j]     = lo + bo;
            out[(size_t)(row0 + 2 * p + 1) * H1C + j] = hi + bo;
        }
    }
}

// ---------------------------------------------------------------------------
// Launch
// ---------------------------------------------------------------------------
extern "C" void kernel_launch(void* const* d_in, const int* in_sizes, int n_in,
                              void* d_out, int out_size) {
    const float* x   = (const float*)d_in[0];
    const float* w1  = (const float*)d_in[1];
    const float* b1  = (const float*)d_in[2];
    const float* lng = (const float*)d_in[3];
    const float* lnb = (const float*)d_in[4];
    const float* w2  = (const float*)d_in[5];
    const float* b2  = (const float*)d_in[6];
    float* out = (float*)d_out;

    cudaFuncSetAttribute(mlp_kernel, cudaFuncAttributeMaxDynamicSharedMemorySize,
                         SMEM_MLP);

    lyndon_setup_kernel<<<1, 32>>>();
    sig_kernel<<<NTOT / NW, 256>>>(x);
    mlp_kernel<<<NTOT / RB, 256, SMEM_MLP>>>(w1, b1, lng, lnb, w2, b2, out);
}